// round 15
// baseline (speedup 1.0000x reference)
#include <cuda_runtime.h>
#include <cuda_fp16.h>
#include <math.h>
#include <stdint.h>

#define B_      2
#define T_      2048
#define D_      2048
#define NH_     8
#define NKV_    4
#define HD_     256
#define SC_     2048
#define WIN_    512
#define SOFTCAP 50.0f
#define NEGINF  -2.3819763e38f
#define QKVW    4096

// ---------------- scratch (device globals; no allocation allowed) ------------
__device__ float  g_qkv[(size_t)B_*T_*QKVW];
__device__ __half g_xh[(size_t)B_*T_*D_];
__device__ __half g_wqkvT[(size_t)QKVW*D_];
__device__ __half g_woT[(size_t)D_*(NH_*HD_)];
__device__ __half g_attn[(size_t)B_*T_*NH_*HD_];
__device__ __half g_kch[(size_t)B_*SC_*NKV_*HD_];
__device__ __half g_vct[(size_t)B_*NKV_*HD_*SC_];
__device__ float2 g_rope[(size_t)SC_*128];

// ---------------- helpers -------------------------------------------------------
__device__ __forceinline__ void f16split(float x, __half& hi, __half& lo) {
    hi = __float2half_rn(x);
    lo = __float2half_rn(x - __half2float(hi));
}

__device__ __forceinline__ uint32_t h2_as_u32(half2 h) {
    return *(uint32_t*)&h;
}

__device__ __forceinline__ void mma_f16(float& d0, float& d1, float& d2, float& d3,
                                        uint32_t a0, uint32_t a1, uint32_t a2, uint32_t a3,
                                        uint32_t b0, uint32_t b1) {
    asm volatile("mma.sync.aligned.m16n8k16.row.col.f32.f16.f16.f32 "
                 "{%0,%1,%2,%3}, {%4,%5,%6,%7}, {%8,%9}, {%0,%1,%2,%3};"
                 : "+f"(d0), "+f"(d1), "+f"(d2), "+f"(d3)
                 : "r"(a0), "r"(a1), "r"(a2), "r"(a3), "r"(b0), "r"(b1));
}

__device__ __forceinline__ void ldmatrix_x4(uint32_t& r0, uint32_t& r1,
                                            uint32_t& r2, uint32_t& r3, uint32_t saddr) {
    asm volatile("ldmatrix.sync.aligned.m8n8.x4.shared.b16 {%0,%1,%2,%3}, [%4];"
                 : "=r"(r0), "=r"(r1), "=r"(r2), "=r"(r3) : "r"(saddr));
}

__device__ __forceinline__ void cpasync16(uint32_t saddr, const void* gptr) {
    asm volatile("cp.async.cg.shared.global [%0], [%1], 16;\n" :: "r"(saddr), "l"(gptr));
}
__device__ __forceinline__ void cpasync_commit() { asm volatile("cp.async.commit_group;"); }
__device__ __forceinline__ void cpasync_wait0()  { asm volatile("cp.async.wait_group 0;"); }
__device__ __forceinline__ void cpasync_wait1()  { asm volatile("cp.async.wait_group 1;"); }

__device__ __forceinline__ float fast_tanh(float x) {
    float xc = fminf(fmaxf(x, -15.0f), 15.0f);
    float e = __expf(-2.0f * xc);
    return (1.0f - e) / (1.0f + e);
}

// ---------------- preprocessing ---------------------------------------------------
__global__ void f2h(const float* __restrict__ in, __half* __restrict__ out, int n4)
{
    const int i = blockIdx.x * 256 + threadIdx.x;
    if (i < n4) {
        float4 v = ((const float4*)in)[i];
        half2 h0 = __floats2half2_rn(v.x, v.y);
        half2 h1 = __floats2half2_rn(v.z, v.w);
        half2* dst = (half2*)(out + (size_t)i * 4);
        dst[0] = h0; dst[1] = h1;
    }
}

__global__ void wtrans_h(const float* __restrict__ w, __half* __restrict__ wt, int K, int N)
{
    __shared__ float tile[32][33];
    const int n0 = blockIdx.x * 32, k0 = blockIdx.y * 32;
    const int tx = threadIdx.x, ty = threadIdx.y;
#pragma unroll
    for (int i = 0; i < 32; i += 8)
        tile[ty + i][tx] = w[(size_t)(k0 + ty + i) * N + n0 + tx];
    __syncthreads();
#pragma unroll
    for (int i = 0; i < 32; i += 8)
        wt[(size_t)(n0 + ty + i) * K + k0 + tx] = __float2half_rn(tile[tx][ty + i]);
}

// ---------------- fp16 tensor-core GEMM (BK=32, 3-stage, ldmatrix) ------------------
#define AST2 40
#define STG2 (128 * AST2)
#define GSMEM (3 * 2 * STG2 * 2)

__global__ void __launch_bounds__(256) gemm_f16(const __half* __restrict__ A,
                                                const __half* __restrict__ Bt,
                                                float* __restrict__ C,
                                                int M, int N, int K)
{
    extern __shared__ __half hs[];
    __half* As = hs;
    __half* Bs = hs + 3 * STG2;

    const int tid  = threadIdx.x;
    const int warp = tid >> 5;
    const int lane = tid & 31;
    const int warpM = warp >> 2;
    const int warpN = warp & 3;
    const int gid = lane >> 2;
    const int tig = lane & 3;

    const int row0 = blockIdx.y * 128;
    const int col0 = blockIdx.x * 128;

    uint32_t sA = (uint32_t)__cvta_generic_to_shared(As);
    uint32_t sB = (uint32_t)__cvta_generic_to_shared(Bs);

    const int ld_r = tid >> 1;
    const int ld_c = (tid & 1) * 2;

    const int a_lrow   = lane & 15;
    const int a_lchunk = (lane >> 4) * 8;
    const int b_lrow   = (lane & 7) + ((lane >> 4) << 3);
    const int b_lchunk = ((lane >> 3) & 1) * 8;

    const int ntiles = K / 32;

    auto load_tile = [&](int kt, int st) {
#pragma unroll
        for (int c = 0; c < 2; c++) {
            cpasync16(sA + (uint32_t)(st * STG2 + ld_r * AST2) * 2 + (ld_c + c) * 16,
                      A + (size_t)(row0 + ld_r) * K + kt * 32 + (ld_c + c) * 8);
            cpasync16(sB + (uint32_t)(st * STG2 + ld_r * AST2) * 2 + (ld_c + c) * 16,
                      Bt + (size_t)(col0 + ld_r) * K + kt * 32 + (ld_c + c) * 8);
        }
    };

    float acc[4][4][4];
#pragma unroll
    for (int i = 0; i < 4; i++)
#pragma unroll
        for (int j = 0; j < 4; j++)
#pragma unroll
            for (int r = 0; r < 4; r++) acc[i][j][r] = 0.0f;

    load_tile(0, 0);
    cpasync_commit();
    load_tile(1, 1);
    cpasync_commit();

    for (int kt = 0; kt < ntiles; kt++) {
        const int st = kt % 3;
        if (kt + 1 < ntiles) cpasync_wait1(); else cpasync_wait0();
        __syncthreads();

        const uint32_t sAst = sA + (uint32_t)(st * STG2) * 2;
        const uint32_t sBst = sB + (uint32_t)(st * STG2) * 2;

#pragma unroll
        for (int ks = 0; ks < 2; ks++) {
            const int kb = ks * 16;
            uint32_t bf[4][2];
#pragma unroll
            for (int p = 0; p < 2; p++) {
                const uint32_t baddr = sBst +
                    (uint32_t)((warpN * 32 + p * 16 + b_lrow) * AST2 + kb + b_lchunk) * 2;
                ldmatrix_x4(bf[2*p][0], bf[2*p][1], bf[2*p+1][0], bf[2*p+1][1], baddr);
            }
#pragma unroll
            for (int mt = 0; mt < 4; mt++) {
                const int rb = warpM * 64 + mt * 16;
                uint32_t a0, a1, a2, a3;
                const uint32_t aaddr = sAst +
                    (uint32_t)((rb + a_lrow) * AST2 + kb + a_lchunk) * 2;
                ldmatrix_x4(a0, a1, a2, a3, aaddr);
#pragma unroll
                for (int nt = 0; nt < 4; nt++)
                    mma_f16(acc[mt][nt][0], acc[mt][nt][1], acc[mt][nt][2], acc[mt][nt][3],
                            a0, a1, a2, a3, bf[nt][0], bf[nt][1]);
            }
        }

        if (kt + 2 < ntiles) {
            load_tile(kt + 2, (kt + 2) % 3);
            cpasync_commit();
        }
    }

#pragma unroll
    for (int mt = 0; mt < 4; mt++) {
        const int r = row0 + warpM * 64 + mt * 16 + gid;
#pragma unroll
        for (int nt = 0; nt < 4; nt++) {
            const int c = col0 + warpN * 32 + nt * 8 + tig * 2;
            *(float2*)(C + (size_t)r * N + c)       = make_float2(acc[mt][nt][0], acc[mt][nt][1]);
            *(float2*)(C + (size_t)(r + 8) * N + c) = make_float2(acc[mt][nt][2], acc[mt][nt][3]);
        }
    }
}

// ---------------- rope table -------------------------------------------------------
__global__ void rope_table_kernel()
{
    const int idx = blockIdx.x * 256 + threadIdx.x;
    const int pos = idx >> 7;
    const int i   = idx & 127;
    const double ts  = pow(10000.0, (double)i / 128.0);
    const double ang = (double)pos / ts;
    double sn, cs;
    sincos(ang, &sn, &cs);
    g_rope[idx] = make_float2((float)cs, (float)sn);
}

// ---------------- K cache merge ------------------------------------------------------
__global__ void merge_k(const float* __restrict__ kcache)
{
    const int i = blockIdx.x * 256 + threadIdx.x;
    float4 v = ((const float4*)kcache)[i];
    half2* dst = (half2*)(g_kch + (size_t)i * 4);
    dst[0] = __floats2half2_rn(v.x, v.y);
    dst[1] = __floats2half2_rn(v.z, v.w);
}

// ---------------- V cache: select + transpose + fp16 ----------------------------------
__global__ void vtrans_cache(const float* __restrict__ vcache, const int* __restrict__ cur)
{
    __shared__ float tile[32][33];
    const int s0 = blockIdx.x * 32, d0 = blockIdx.y * 32;
    const int bk = blockIdx.z;
    const int b = bk / NKV_, kv = bk % NKV_;
    const int tx = threadIdx.x, ty = threadIdx.y;
    const int ci = *cur;
#pragma unroll
    for (int i = 0; i < 32; i += 8) {
        const int s = s0 + ty + i;
        const int t = s - ci;
        const float v = (t >= 0 && t < T_)
            ? g_qkv[((size_t)b * T_ + t) * QKVW + 3072 + kv * HD_ + d0 + tx]
            : vcache[(((size_t)b * SC_ + s) * NKV_ + kv) * HD_ + d0 + tx];
        tile[ty + i][tx] = v;
    }
    __syncthreads();
#pragma unroll
    for (int i = 0; i < 32; i += 8) {
        const int d = d0 + ty + i;
        g_vct[((size_t)(b * NKV_ + kv) * HD_ + d) * SC_ + s0 + tx] =
            __float2half_rn(tile[tx][ty + i]);
    }
}

// ---------------- RMSNorm + RoPE (fused q & k, one launch) ----------------------------
__global__ void normrope_kernel(float* __restrict__ qkv,
                                const float* __restrict__ qns,
                                const float* __restrict__ kns,
                                const int* __restrict__ seg,
                                const int* __restrict__ cur)
{
    const int bt = blockIdx.x;
    const int hy = blockIdx.y;
    const int d  = threadIdx.x;

    const bool is_k = hy >= NH_;
    const int h = is_k ? hy - NH_ : hy;
    const int in_off = is_k ? 2048 : 0;
    const float* scale = is_k ? kns : qns;

    const size_t in_idx = (size_t)bt * QKVW + in_off + h * HD_ + d;
    const float v = qkv[in_idx];

    float ss = v * v;
#pragma unroll
    for (int o = 16; o; o >>= 1) ss += __shfl_xor_sync(0xffffffffu, ss, o);
    __shared__ float red[8];
    __shared__ float s_ms;
    __shared__ float sh[HD_];
    const int lane = d & 31, w = d >> 5;
    if (lane == 0) red[w] = ss;
    __syncthreads();
    if (d == 0) {
        float t = 0.0f;
#pragma unroll
        for (int i = 0; i < 8; i++) t += red[i];
        s_ms = rsqrtf(t / (float)HD_ + 1e-6f);
    }
    __syncthreads();

    const float n = v * s_ms * (1.0f + scale[d]);
    sh[d] = n;
    __syncthreads();

    int pos = seg[bt];
    if (pos < 0) pos = 0;
    if (pos > SC_ - 1) pos = SC_ - 1;
    const int i = d & 127;
    const float2 cssn = g_rope[pos * 128 + i];
    const float x1 = sh[i], x2 = sh[i + 128];
    const float r = (d < 128) ? (x1 * cssn.x - x2 * cssn.y)
                              : (x2 * cssn.x + x1 * cssn.y);

    if (is_k) {
        const int b = bt / T_, t = bt - b * T_;
        const int slot = *cur + t;
        if (slot < SC_)
            g_kch[(((size_t)b * SC_ + slot) * NKV_ + h) * HD_ + d] = __float2half_rn(r);
    } else {
        qkv[in_idx] = r;
    }
}

// ---------------- fp16 flash attention: 64-query tiles, 512 threads --------------------
#define QT  64     // queries per block
#define QKH 264
#define VTS 40
#define SSS 36

struct AttnSmemH {
    __half Qhi[QT * QKH];
    __half Qlo[QT * QKH];
    __half Kh [32 * QKH];
    __half Vt [256 * VTS];
    float  Ss [QT * SSS];
    int   pos[QT];
    int   srange[2];
};

__global__ void __launch_bounds__(512, 1) attn_f16(const int* __restrict__ seg)
{
    extern __shared__ char smem_raw[];
    AttnSmemH& sm = *reinterpret_cast<AttnSmemH*>(smem_raw);

    const int tid  = threadIdx.x;
    const int warp = tid >> 5;
    const int lane = tid & 31;
    const int gid  = lane >> 2;
    const int tig  = lane & 3;
    const int warpM = warp >> 2;   // 0..3 (16 rows each)
    const int warpN = warp & 3;    // 0..3

    const int q0 = blockIdx.x * QT;
    const int h  = blockIdx.y;
    const int b  = blockIdx.z;
    const int kvh = h / (NH_ / NKV_);

    // ---- Q load: 64 x 256 floats = 4096 float4, 512 threads x 8 ----
    const float* qbase = g_qkv + ((size_t)b * T_ + q0) * QKVW + h * HD_;
    const float qscale = 0.0625f;
#pragma unroll
    for (int j = 0; j < 8; j++) {
        const int fi = tid + j * 512;
        const int r = fi >> 6, c4 = (fi & 63) * 4;
        float4 v = *(const float4*)(qbase + (size_t)r * QKVW + c4);
        __half h0, l0, h1, l1, h2, l2, h3, l3;
        f16split(v.x * qscale, h0, l0);
        f16split(v.y * qscale, h1, l1);
        f16split(v.z * qscale, h2, l2);
        f16split(v.w * qscale, h3, l3);
        *(half2*)&sm.Qhi[r*QKH + c4]     = __halves2half2(h0, h1);
        *(half2*)&sm.Qhi[r*QKH + c4 + 2] = __halves2half2(h2, h3);
        *(half2*)&sm.Qlo[r*QKH + c4]     = __halves2half2(l0, l1);
        *(half2*)&sm.Qlo[r*QKH + c4 + 2] = __halves2half2(l2, l3);
    }
    if (tid < QT)
        sm.pos[tid] = seg[b * T_ + q0 + tid];
    __syncthreads();
    if (tid == 0) {
        int mn = sm.pos[0], mx = sm.pos[0];
        for (int j = 1; j < QT; j++) { mn = min(mn, sm.pos[j]); mx = max(mx, sm.pos[j]); }
        int lo = mn - (WIN_ - 1); if (lo < 0) lo = 0;
        int hi = mx; if (hi > SC_ - 1) hi = SC_ - 1;
        sm.srange[0] = lo & ~31;
        sm.srange[1] = hi;
    }
    __syncthreads();
    const int s_lo = sm.srange[0], s_hi = sm.srange[1];

    const int arow = warpM * 16 + gid;

    float m0 = -1e30f, m1 = -1e30f, l0r = 0.0f, l1r = 0.0f;

    float o[8][4];
#pragma unroll
    for (int nf = 0; nf < 8; nf++)
#pragma unroll
        for (int r = 0; r < 4; r++) o[nf][r] = 0.0f;

    const __half* khbase = g_kch + ((size_t)b * SC_ * NKV_ + kvh) * HD_;
    const __half* vtbase = g_vct + (size_t)(b * NKV_ + kvh) * HD_ * SC_;

    for (int s0 = s_lo; s0 <= s_hi; s0 += 32) {
        // ---- K tile: 32x256 halves = 1024 uint4; V tile: 256x32 = 1024 uint4 ----
#pragma unroll
        for (int j = 0; j < 2; j++) {
            const int fi = tid + j * 512;
            const int r = fi >> 5, c8 = (fi & 31) * 8;
            *(uint4*)&sm.Kh[r*QKH + c8] =
                *(const uint4*)(khbase + (size_t)(s0 + r) * NKV_ * HD_ + c8);
        }
#pragma unroll
        for (int j = 0; j < 2; j++) {
            const int fi = tid + j * 512;
            const int d = fi >> 2, c8 = (fi & 3) * 8;
            *(uint4*)&sm.Vt[d*VTS + c8] =
                *(const uint4*)(vtbase + (size_t)d * SC_ + s0 + c8);
        }
        __syncthreads();                               // sync 1

        // ---- QK^T ----
        float sc0 = 0.f, sc1 = 0.f, sc2 = 0.f, sc3 = 0.f;
        const int bcol = warpN * 8 + gid;
#pragma unroll
        for (int kb = 0; kb < HD_; kb += 16) {
            const uint32_t qh0 = *(const uint32_t*)&sm.Qhi[(arow)    *QKH + kb + tig*2];
            const uint32_t qh1 = *(const uint32_t*)&sm.Qhi[(arow + 8)*QKH + kb + tig*2];
            const uint32_t qh2 = *(const uint32_t*)&sm.Qhi[(arow)    *QKH + kb + 8 + tig*2];
            const uint32_t qh3 = *(const uint32_t*)&sm.Qhi[(arow + 8)*QKH + kb + 8 + tig*2];
            const uint32_t ql0 = *(const uint32_t*)&sm.Qlo[(arow)    *QKH + kb + tig*2];
            const uint32_t ql1 = *(const uint32_t*)&sm.Qlo[(arow + 8)*QKH + kb + tig*2];
            const uint32_t ql2 = *(const uint32_t*)&sm.Qlo[(arow)    *QKH + kb + 8 + tig*2];
            const uint32_t ql3 = *(const uint32_t*)&sm.Qlo[(arow + 8)*QKH + kb + 8 + tig*2];
            const uint32_t k0 = *(const uint32_t*)&sm.Kh[bcol*QKH + kb + tig*2];
            const uint32_t k1 = *(const uint32_t*)&sm.Kh[bcol*QKH + kb + 8 + tig*2];
            mma_f16(sc0, sc1, sc2, sc3, qh0, qh1, qh2, qh3, k0, k1);
            mma_f16(sc0, sc1, sc2, sc3, ql0, ql1, ql2, ql3, k0, k1);
        }

        // ---- softcap + mask, exchange via Ss ----
        {
            const int c0 = warpN * 8 + tig * 2;
            const int sa = s0 + c0, sb2 = s0 + c0 + 1;
            const int qp0 = sm.pos[arow], qp1 = sm.pos[arow + 8];
            const float v0 = SOFTCAP * fast_tanh(sc0 * (1.0f / SOFTCAP));
            const float v1 = SOFTCAP * fast_tanh(sc1 * (1.0f / SOFTCAP));
            const float v2 = SOFTCAP * fast_tanh(sc2 * (1.0f / SOFTCAP));
            const float v3 = SOFTCAP * fast_tanh(sc3 * (1.0f / SOFTCAP));
            sm.Ss[(arow)    *SSS + c0    ] = (sa  <= qp0 && qp0 - sa  < WIN_) ? v0 : NEGINF;
            sm.Ss[(arow)    *SSS + c0 + 1] = (sb2 <= qp0 && qp0 - sb2 < WIN_) ? v1 : NEGINF;
            sm.Ss[(arow + 8)*SSS + c0    ] = (sa  <= qp1 && qp1 - sa  < WIN_) ? v2 : NEGINF;
            sm.Ss[(arow + 8)*SSS + c0 + 1] = (sb2 <= qp1 && qp1 - sb2 < WIN_) ? v3 : NEGINF;
        }
        __syncthreads();                               // sync 2

        // ---- register softmax ----
        float s0v[8], s1v[8];
#pragma unroll
        for (int g = 0; g < 4; g++) {
            const float2 a = *(const float2*)&sm.Ss[(arow)    *SSS + g * 8 + tig * 2];
            const float2 c = *(const float2*)&sm.Ss[(arow + 8)*SSS + g * 8 + tig * 2];
            s0v[g*2] = a.x; s0v[g*2+1] = a.y;
            s1v[g*2] = c.x; s1v[g*2+1] = c.y;
        }
        float mx0 = s0v[0], mx1 = s1v[0];
#pragma unroll
        for (int i = 1; i < 8; i++) { mx0 = fmaxf(mx0, s0v[i]); mx1 = fmaxf(mx1, s1v[i]); }
        mx0 = fmaxf(mx0, __shfl_xor_sync(0xffffffffu, mx0, 1));
        mx0 = fmaxf(mx0, __shfl_xor_sync(0xffffffffu, mx0, 2));
        mx1 = fmaxf(mx1, __shfl_xor_sync(0xffffffffu, mx1, 1));
        mx1 = fmaxf(mx1, __shfl_xor_sync(0xffffffffu, mx1, 2));

        const float mn0 = fmaxf(m0, mx0);
        const float mn1 = fmaxf(m1, mx1);
        const float a0 = __expf(m0 - mn0);
        const float a1 = __expf(m1 - mn1);

        float p0[8], p1[8];
        float ls0 = 0.0f, ls1 = 0.0f;
#pragma unroll
        for (int i = 0; i < 8; i++) {
            p0[i] = __expf(s0v[i] - mn0);
            p1[i] = __expf(s1v[i] - mn1);
            ls0 += p0[i]; ls1 += p1[i];
        }
        ls0 += __shfl_xor_sync(0xffffffffu, ls0, 1);
        ls0 += __shfl_xor_sync(0xffffffffu, ls0, 2);
        ls1 += __shfl_xor_sync(0xffffffffu, ls1, 1);
        ls1 += __shfl_xor_sync(0xffffffffu, ls1, 2);

        m0 = mn0; m1 = mn1;
        l0r = l0r * a0 + ls0;
        l1r = l1r * a1 + ls1;

        // ---- rescale O, pack P fragments, P @ V ----
#pragma unroll
        for (int nf = 0; nf < 8; nf++) {
            o[nf][0] *= a0; o[nf][1] *= a0;
            o[nf][2] *= a1; o[nf][3] *= a1;
        }
#pragma unroll
        for (int ks = 0; ks < 2; ks++) {
            const int kb = ks * 16;
            const uint32_t pa0 = h2_as_u32(__floats2half2_rn(p0[ks*4+0], p0[ks*4+1]));
            const uint32_t pa1 = h2_as_u32(__floats2half2_rn(p1[ks*4+0], p1[ks*4+1]));
            const uint32_t pa2 = h2_as_u32(__floats2half2_rn(p0[ks*4+2], p0[ks*4+3]));
            const uint32_t pa3 = h2_as_u32(__floats2half2_rn(p1[ks*4+2], p1[ks*4+3]));
#pragma unroll
            for (int nf = 0; nf < 8; nf++) {
                const int col = warpN * 64 + nf * 8 + gid;
                const uint32_t b0 = *(const uint32_t*)&sm.Vt[col*VTS + kb + tig*2];
                const uint32_t b1 = *(const uint32_t*)&sm.Vt[col*VTS + kb + 8 + tig*2];
                mma_f16(o[nf][0], o[nf][1], o[nf][2], o[nf][3],
                        pa0, pa1, pa2, pa3, b0, b1);
            }
        }
        __syncthreads();                               // sync 3
    }

    const float li0 = 1.0f / l0r;
    const float li1 = 1.0f / l1r;
    const int row0g = q0 + arow;
#pragma unroll
    for (int nf = 0; nf < 8; nf++) {
        const int col = warpN * 64 + nf * 8 + tig * 2;
        __half* p0 = g_attn + (((size_t)b * T_ + row0g)     * NH_ + h) * HD_ + col;
        __half* p1 = g_attn + (((size_t)b * T_ + row0g + 8) * NH_ + h) * HD_ + col;
        *(half2*)p0 = __floats2half2_rn(o[nf][0] * li0, o[nf][1] * li0);
        *(half2*)p1 = __floats2half2_rn(o[nf][2] * li1, o[nf][3] * li1);
    }
}

// ---------------- launcher ----------------------------------------------------------
extern "C" void kernel_launch(void* const* d_in, const int* in_sizes, int n_in,
                              void* d_out, int out_size)
{
    const float* x      = (const float*)d_in[0];
    const int*   seg    = (const int*)  d_in[1];
    const int*   cur    = (const int*)  d_in[2];
    const float* wq     = (const float*)d_in[3];
    const float* wk     = (const float*)d_in[4];
    const float* wv     = (const float*)d_in[5];
    const float* wo     = (const float*)d_in[6];
    const float* qns    = (const float*)d_in[7];
    const float* kns    = (const float*)d_in[8];
    const float* kcache = (const float*)d_in[9];
    const float* vcache = (const float*)d_in[10];
    float* out = (float*)d_out;

    float *qkvp;
    __half *xh, *wqkvT, *woT, *attnp;
    cudaGetSymbolAddress((void**)&qkvp,  g_qkv);
    cudaGetSymbolAddress((void**)&xh,    g_xh);
    cudaGetSymbolAddress((void**)&wqkvT, g_wqkvT);
    cudaGetSymbolAddress((void**)&woT,   g_woT);
    cudaGetSymbolAddress((void**)&attnp, g_attn);

    const int M = B_ * T_;

    f2h<<<((B_*T_*D_/4) + 255)/256, 256>>>(x, xh, B_*T_*D_/4);
    wtrans_h<<<dim3(2048/32, D_/32), dim3(32,8)>>>(wq, wqkvT,                   D_, 2048);
    wtrans_h<<<dim3(1024/32, D_/32), dim3(32,8)>>>(wk, wqkvT + (size_t)2048*D_, D_, 1024);
    wtrans_h<<<dim3(1024/32, D_/32), dim3(32,8)>>>(wv, wqkvT + (size_t)3072*D_, D_, 1024);
    wtrans_h<<<dim3(D_/32, (NH_*HD_)/32), dim3(32,8)>>>(wo, woT, NH_*HD_, D_);

    rope_table_kernel<<<(SC_ * 128) / 256, 256>>>();

    cudaFuncSetAttribute(gemm_f16, cudaFuncAttributeMaxDynamicSharedMemorySize, GSMEM);

    gemm_f16<<<dim3(QKVW/128, M/128), 256, GSMEM>>>(xh, wqkvT, qkvp, M, QKVW, D_);

    merge_k<<<(B_*SC_*NKV_*HD_/4)/256, 256>>>(kcache);
    vtrans_cache<<<dim3(SC_/32, HD_/32, B_*NKV_), dim3(32,8)>>>(vcache, cur);

    normrope_kernel<<<dim3(M, NH_ + NKV_), 256>>>(qkvp, qns, kns, seg, cur);

    cudaFuncSetAttribute(attn_f16, cudaFuncAttributeMaxDynamicSharedMemorySize,
                         (int)sizeof(AttnSmemH));
    attn_f16<<<dim3(T_/QT, NH_, B_), 512, sizeof(AttnSmemH)>>>(seg);

    gemm_f16<<<dim3(D_/128, M/128), 256, GSMEM>>>(attnp, woT, out, M, D_, NH_*HD_);
}

// round 16
// speedup vs baseline: 1.0629x; 1.0629x over previous
#include <cuda_runtime.h>
#include <cuda_fp16.h>
#include <math.h>
#include <stdint.h>

#define B_      2
#define T_      2048
#define D_      2048
#define NH_     8
#define NKV_    4
#define HD_     256
#define SC_     2048
#define WIN_    512
#define SOFTCAP 50.0f
#define NEGINF  -2.3819763e38f
#define QKVW    4096

// ---------------- scratch (device globals; no allocation allowed) ------------
__device__ float  g_qkv[(size_t)B_*T_*QKVW];
__device__ __half g_xh[(size_t)B_*T_*D_];
__device__ __half g_wqkvT[(size_t)QKVW*D_];
__device__ __half g_woT[(size_t)D_*(NH_*HD_)];
__device__ __half g_attn[(size_t)B_*T_*NH_*HD_];
__device__ __half g_kch[(size_t)B_*SC_*NKV_*HD_];
__device__ __half g_vct[(size_t)B_*NKV_*HD_*SC_];
__device__ float2 g_rope[(size_t)SC_*128];

// ---------------- helpers -------------------------------------------------------
__device__ __forceinline__ void f16split(float x, __half& hi, __half& lo) {
    hi = __float2half_rn(x);
    lo = __float2half_rn(x - __half2float(hi));
}

__device__ __forceinline__ uint32_t h2_as_u32(half2 h) {
    return *(uint32_t*)&h;
}

__device__ __forceinline__ void mma_f16(float& d0, float& d1, float& d2, float& d3,
                                        uint32_t a0, uint32_t a1, uint32_t a2, uint32_t a3,
                                        uint32_t b0, uint32_t b1) {
    asm volatile("mma.sync.aligned.m16n8k16.row.col.f32.f16.f16.f32 "
                 "{%0,%1,%2,%3}, {%4,%5,%6,%7}, {%8,%9}, {%0,%1,%2,%3};"
                 : "+f"(d0), "+f"(d1), "+f"(d2), "+f"(d3)
                 : "r"(a0), "r"(a1), "r"(a2), "r"(a3), "r"(b0), "r"(b1));
}

__device__ __forceinline__ void ldmatrix_x4(uint32_t& r0, uint32_t& r1,
                                            uint32_t& r2, uint32_t& r3, uint32_t saddr) {
    asm volatile("ldmatrix.sync.aligned.m8n8.x4.shared.b16 {%0,%1,%2,%3}, [%4];"
                 : "=r"(r0), "=r"(r1), "=r"(r2), "=r"(r3) : "r"(saddr));
}

__device__ __forceinline__ void cpasync16(uint32_t saddr, const void* gptr) {
    asm volatile("cp.async.cg.shared.global [%0], [%1], 16;\n" :: "r"(saddr), "l"(gptr));
}
__device__ __forceinline__ void cpasync_commit() { asm volatile("cp.async.commit_group;"); }
__device__ __forceinline__ void cpasync_wait0()  { asm volatile("cp.async.wait_group 0;"); }
__device__ __forceinline__ void cpasync_wait1()  { asm volatile("cp.async.wait_group 1;"); }

__device__ __forceinline__ float fast_tanh(float x) {
    float xc = fminf(fmaxf(x, -15.0f), 15.0f);
    float e = __expf(-2.0f * xc);
    return (1.0f - e) / (1.0f + e);
}

// ---------------- preprocessing ---------------------------------------------------
__global__ void f2h(const float* __restrict__ in, __half* __restrict__ out, int n4)
{
    const int i = blockIdx.x * 256 + threadIdx.x;
    if (i < n4) {
        float4 v = ((const float4*)in)[i];
        half2 h0 = __floats2half2_rn(v.x, v.y);
        half2 h1 = __floats2half2_rn(v.z, v.w);
        half2* dst = (half2*)(out + (size_t)i * 4);
        dst[0] = h0; dst[1] = h1;
    }
}

__global__ void wtrans_h(const float* __restrict__ w, __half* __restrict__ wt, int K, int N)
{
    __shared__ float tile[32][33];
    const int n0 = blockIdx.x * 32, k0 = blockIdx.y * 32;
    const int tx = threadIdx.x, ty = threadIdx.y;
#pragma unroll
    for (int i = 0; i < 32; i += 8)
        tile[ty + i][tx] = w[(size_t)(k0 + ty + i) * N + n0 + tx];
    __syncthreads();
#pragma unroll
    for (int i = 0; i < 32; i += 8)
        wt[(size_t)(n0 + ty + i) * K + k0 + tx] = __float2half_rn(tile[tx][ty + i]);
}

// ---------------- fp16 tensor-core GEMM (BK=32, 3-stage, ldmatrix) ------------------
#define AST2 40
#define STG2 (128 * AST2)
#define GSMEM (3 * 2 * STG2 * 2)

__global__ void __launch_bounds__(256) gemm_f16(const __half* __restrict__ A,
                                                const __half* __restrict__ Bt,
                                                float* __restrict__ C,
                                                int M, int N, int K)
{
    extern __shared__ __half hs[];
    __half* As = hs;
    __half* Bs = hs + 3 * STG2;

    const int tid  = threadIdx.x;
    const int warp = tid >> 5;
    const int lane = tid & 31;
    const int warpM = warp >> 2;
    const int warpN = warp & 3;
    const int gid = lane >> 2;
    const int tig = lane & 3;

    const int row0 = blockIdx.y * 128;
    const int col0 = blockIdx.x * 128;

    uint32_t sA = (uint32_t)__cvta_generic_to_shared(As);
    uint32_t sB = (uint32_t)__cvta_generic_to_shared(Bs);

    const int ld_r = tid >> 1;
    const int ld_c = (tid & 1) * 2;

    const int a_lrow   = lane & 15;
    const int a_lchunk = (lane >> 4) * 8;
    const int b_lrow   = (lane & 7) + ((lane >> 4) << 3);
    const int b_lchunk = ((lane >> 3) & 1) * 8;

    const int ntiles = K / 32;

    auto load_tile = [&](int kt, int st) {
#pragma unroll
        for (int c = 0; c < 2; c++) {
            cpasync16(sA + (uint32_t)(st * STG2 + ld_r * AST2) * 2 + (ld_c + c) * 16,
                      A + (size_t)(row0 + ld_r) * K + kt * 32 + (ld_c + c) * 8);
            cpasync16(sB + (uint32_t)(st * STG2 + ld_r * AST2) * 2 + (ld_c + c) * 16,
                      Bt + (size_t)(col0 + ld_r) * K + kt * 32 + (ld_c + c) * 8);
        }
    };

    float acc[4][4][4];
#pragma unroll
    for (int i = 0; i < 4; i++)
#pragma unroll
        for (int j = 0; j < 4; j++)
#pragma unroll
            for (int r = 0; r < 4; r++) acc[i][j][r] = 0.0f;

    load_tile(0, 0);
    cpasync_commit();
    load_tile(1, 1);
    cpasync_commit();

    for (int kt = 0; kt < ntiles; kt++) {
        const int st = kt % 3;
        if (kt + 1 < ntiles) cpasync_wait1(); else cpasync_wait0();
        __syncthreads();

        const uint32_t sAst = sA + (uint32_t)(st * STG2) * 2;
        const uint32_t sBst = sB + (uint32_t)(st * STG2) * 2;

#pragma unroll
        for (int ks = 0; ks < 2; ks++) {
            const int kb = ks * 16;
            uint32_t bf[4][2];
#pragma unroll
            for (int p = 0; p < 2; p++) {
                const uint32_t baddr = sBst +
                    (uint32_t)((warpN * 32 + p * 16 + b_lrow) * AST2 + kb + b_lchunk) * 2;
                ldmatrix_x4(bf[2*p][0], bf[2*p][1], bf[2*p+1][0], bf[2*p+1][1], baddr);
            }
#pragma unroll
            for (int mt = 0; mt < 4; mt++) {
                const int rb = warpM * 64 + mt * 16;
                uint32_t a0, a1, a2, a3;
                const uint32_t aaddr = sAst +
                    (uint32_t)((rb + a_lrow) * AST2 + kb + a_lchunk) * 2;
                ldmatrix_x4(a0, a1, a2, a3, aaddr);
#pragma unroll
                for (int nt = 0; nt < 4; nt++)
                    mma_f16(acc[mt][nt][0], acc[mt][nt][1], acc[mt][nt][2], acc[mt][nt][3],
                            a0, a1, a2, a3, bf[nt][0], bf[nt][1]);
            }
        }

        if (kt + 2 < ntiles) {
            load_tile(kt + 2, (kt + 2) % 3);
            cpasync_commit();
        }
    }

#pragma unroll
    for (int mt = 0; mt < 4; mt++) {
        const int r = row0 + warpM * 64 + mt * 16 + gid;
#pragma unroll
        for (int nt = 0; nt < 4; nt++) {
            const int c = col0 + warpN * 32 + nt * 8 + tig * 2;
            *(float2*)(C + (size_t)r * N + c)       = make_float2(acc[mt][nt][0], acc[mt][nt][1]);
            *(float2*)(C + (size_t)(r + 8) * N + c) = make_float2(acc[mt][nt][2], acc[mt][nt][3]);
        }
    }
}

// ---------------- rope table -------------------------------------------------------
__global__ void rope_table_kernel()
{
    const int idx = blockIdx.x * 256 + threadIdx.x;
    const int pos = idx >> 7;
    const int i   = idx & 127;
    const double ts  = pow(10000.0, (double)i / 128.0);
    const double ang = (double)pos / ts;
    double sn, cs;
    sincos(ang, &sn, &cs);
    g_rope[idx] = make_float2((float)cs, (float)sn);
}

// ---------------- K cache merge ------------------------------------------------------
__global__ void merge_k(const float* __restrict__ kcache)
{
    const int i = blockIdx.x * 256 + threadIdx.x;
    float4 v = ((const float4*)kcache)[i];
    half2* dst = (half2*)(g_kch + (size_t)i * 4);
    dst[0] = __floats2half2_rn(v.x, v.y);
    dst[1] = __floats2half2_rn(v.z, v.w);
}

// ---------------- V cache: select + transpose + fp16 ----------------------------------
__global__ void vtrans_cache(const float* __restrict__ vcache, const int* __restrict__ cur)
{
    __shared__ float tile[32][33];
    const int s0 = blockIdx.x * 32, d0 = blockIdx.y * 32;
    const int bk = blockIdx.z;
    const int b = bk / NKV_, kv = bk % NKV_;
    const int tx = threadIdx.x, ty = threadIdx.y;
    const int ci = *cur;
#pragma unroll
    for (int i = 0; i < 32; i += 8) {
        const int s = s0 + ty + i;
        const int t = s - ci;
        const float v = (t >= 0 && t < T_)
            ? g_qkv[((size_t)b * T_ + t) * QKVW + 3072 + kv * HD_ + d0 + tx]
            : vcache[(((size_t)b * SC_ + s) * NKV_ + kv) * HD_ + d0 + tx];
        tile[ty + i][tx] = v;
    }
    __syncthreads();
#pragma unroll
    for (int i = 0; i < 32; i += 8) {
        const int d = d0 + ty + i;
        g_vct[((size_t)(b * NKV_ + kv) * HD_ + d) * SC_ + s0 + tx] =
            __float2half_rn(tile[tx][ty + i]);
    }
}

// ---------------- RMSNorm + RoPE: one WARP per (bt, head), no barriers ----------------
// 256 threads = 8 warps = 8 (bt,head) units. Total units = B*T*(NH+NKV) = 49152.
__global__ void __launch_bounds__(256) normrope_warp(float* __restrict__ qkv,
                                                     const float* __restrict__ qns,
                                                     const float* __restrict__ kns,
                                                     const int* __restrict__ seg,
                                                     const int* __restrict__ cur)
{
    const int gw   = blockIdx.x * 8 + (threadIdx.x >> 5);
    const int lane = threadIdx.x & 31;
    const int bt = gw / (NH_ + NKV_);
    const int hy = gw - bt * (NH_ + NKV_);

    const bool is_k = hy >= NH_;
    const int h = is_k ? hy - NH_ : hy;
    const int in_off = is_k ? 2048 : 0;
    const float* scale = is_k ? kns : qns;

    float* base = qkv + (size_t)bt * QKVW + in_off + h * HD_;
    const float4 va = *(const float4*)(base + lane * 4);          // dims d..d+3   (d<128)
    const float4 vb = *(const float4*)(base + 128 + lane * 4);    // dims d+128..

    float ss = va.x*va.x + va.y*va.y + va.z*va.z + va.w*va.w
             + vb.x*vb.x + vb.y*vb.y + vb.z*vb.z + vb.w*vb.w;
#pragma unroll
    for (int o = 16; o; o >>= 1) ss += __shfl_xor_sync(0xffffffffu, ss, o);
    const float msi = rsqrtf(ss * (1.0f / (float)HD_) + 1e-6f);

    const float4 sa = *(const float4*)(scale + lane * 4);
    const float4 sb = *(const float4*)(scale + 128 + lane * 4);

    float n1[4], n2[4];
    n1[0] = va.x * msi * (1.0f + sa.x);
    n1[1] = va.y * msi * (1.0f + sa.y);
    n1[2] = va.z * msi * (1.0f + sa.z);
    n1[3] = va.w * msi * (1.0f + sa.w);
    n2[0] = vb.x * msi * (1.0f + sb.x);
    n2[1] = vb.y * msi * (1.0f + sb.y);
    n2[2] = vb.z * msi * (1.0f + sb.z);
    n2[3] = vb.w * msi * (1.0f + sb.w);

    int pos = seg[bt];
    if (pos < 0) pos = 0;
    if (pos > SC_ - 1) pos = SC_ - 1;

    float r1[4], r2[4];
#pragma unroll
    for (int j = 0; j < 4; j++) {
        const float2 cs = g_rope[pos * 128 + lane * 4 + j];
        r1[j] = n1[j] * cs.x - n2[j] * cs.y;
        r2[j] = n2[j] * cs.x + n1[j] * cs.y;
    }

    if (is_k) {
        const int b = bt / T_, t = bt - b * T_;
        const int slot = *cur + t;
        if (slot < SC_) {
            __half* kb = g_kch + (((size_t)b * SC_ + slot) * NKV_ + h) * HD_;
            *(half2*)(kb + lane * 4)       = __floats2half2_rn(r1[0], r1[1]);
            *(half2*)(kb + lane * 4 + 2)   = __floats2half2_rn(r1[2], r1[3]);
            *(half2*)(kb + 128 + lane * 4)     = __floats2half2_rn(r2[0], r2[1]);
            *(half2*)(kb + 128 + lane * 4 + 2) = __floats2half2_rn(r2[2], r2[3]);
        }
    } else {
        *(float4*)(base + lane * 4)       = make_float4(r1[0], r1[1], r1[2], r1[3]);
        *(float4*)(base + 128 + lane * 4) = make_float4(r2[0], r2[1], r2[2], r2[3]);
    }
}

// ---------------- fp16 flash attention: register softmax + K/V register prefetch -------
#define QKH 264
#define VTS 40
#define SSS 36

struct AttnSmemH {
    __half Qhi[32 * QKH];
    __half Qlo[32 * QKH];
    __half Kh [32 * QKH];
    __half Vt [256 * VTS];
    float  Ss [32 * SSS];
    int   pos[32];
    int   srange[2];
};

__global__ void __launch_bounds__(256, 2) attn_f16(const int* __restrict__ seg)
{
    extern __shared__ char smem_raw[];
    AttnSmemH& sm = *reinterpret_cast<AttnSmemH*>(smem_raw);

    const int tid  = threadIdx.x;
    const int warp = tid >> 5;
    const int lane = tid & 31;
    const int gid  = lane >> 2;
    const int tig  = lane & 3;
    const int warpM = warp >> 2;
    const int warpN = warp & 3;

    const int q0 = blockIdx.x * 32;
    const int h  = blockIdx.y;
    const int b  = blockIdx.z;
    const int kvh = h / (NH_ / NKV_);

    const float* qbase = g_qkv + ((size_t)b * T_ + q0) * QKVW + h * HD_;
    const float qscale = 0.0625f;
#pragma unroll
    for (int j = 0; j < 8; j++) {
        const int fi = tid + j * 256;
        const int r = fi >> 6, c4 = (fi & 63) * 4;
        float4 v = *(const float4*)(qbase + (size_t)r * QKVW + c4);
        __half h0, l0, h1, l1, h2, l2, h3, l3;
        f16split(v.x * qscale, h0, l0);
        f16split(v.y * qscale, h1, l1);
        f16split(v.z * qscale, h2, l2);
        f16split(v.w * qscale, h3, l3);
        *(half2*)&sm.Qhi[r*QKH + c4]     = __halves2half2(h0, h1);
        *(half2*)&sm.Qhi[r*QKH + c4 + 2] = __halves2half2(h2, h3);
        *(half2*)&sm.Qlo[r*QKH + c4]     = __halves2half2(l0, l1);
        *(half2*)&sm.Qlo[r*QKH + c4 + 2] = __halves2half2(l2, l3);
    }
    if (tid < 32)
        sm.pos[tid] = seg[b * T_ + q0 + tid];
    __syncthreads();
    if (tid == 0) {
        int mn = sm.pos[0], mx = sm.pos[0];
        for (int j = 1; j < 32; j++) { mn = min(mn, sm.pos[j]); mx = max(mx, sm.pos[j]); }
        int lo = mn - (WIN_ - 1); if (lo < 0) lo = 0;
        int hi = mx; if (hi > SC_ - 1) hi = SC_ - 1;
        sm.srange[0] = lo & ~31;
        sm.srange[1] = hi;
    }
    __syncthreads();
    const int s_lo = sm.srange[0], s_hi = sm.srange[1];

    const int arow = warpM * 16 + gid;

    float m0 = -1e30f, m1 = -1e30f, l0r = 0.0f, l1r = 0.0f;

    float o[8][4];
#pragma unroll
    for (int nf = 0; nf < 8; nf++)
#pragma unroll
        for (int r = 0; r < 4; r++) o[nf][r] = 0.0f;

    const __half* khbase = g_kch + ((size_t)b * SC_ * NKV_ + kvh) * HD_;
    const __half* vtbase = g_vct + (size_t)(b * NKV_ + kvh) * HD_ * SC_;

    // K/V tile register staging
    uint4 kpre[4], vpre[4];

    // per-thread load coordinates (constant across tiles)
    const int k_r[4]  = { (tid+0) >> 5, (tid+256) >> 5, (tid+512) >> 5, (tid+768) >> 5 };
    const int k_c8    = (tid & 31) * 8;
    const int v_d[4]  = { (tid+0) >> 2, (tid+256) >> 2, (tid+512) >> 2, (tid+768) >> 2 };
    const int v_c8    = (tid & 3) * 8;

    auto load_kv = [&](int s0) {
#pragma unroll
        for (int j = 0; j < 4; j++) {
            kpre[j] = *(const uint4*)(khbase + (size_t)(s0 + k_r[j]) * NKV_ * HD_ + k_c8);
            vpre[j] = *(const uint4*)(vtbase + (size_t)v_d[j] * SC_ + s0 + v_c8);
        }
    };
    auto store_kv = [&]() {
#pragma unroll
        for (int j = 0; j < 4; j++) {
            *(uint4*)&sm.Kh[k_r[j]*QKH + k_c8] = kpre[j];
            *(uint4*)&sm.Vt[v_d[j]*VTS + v_c8] = vpre[j];
        }
    };

    load_kv(s_lo);
    store_kv();
    __syncthreads();

    for (int s0 = s_lo; s0 <= s_hi; s0 += 32) {
        const bool has_next = (s0 + 32) <= s_hi;
        if (has_next) load_kv(s0 + 32);     // prefetch next tile into registers

        // ---- QK^T ----
        float sc0 = 0.f, sc1 = 0.f, sc2 = 0.f, sc3 = 0.f;
        const int bcol = warpN * 8 + gid;
#pragma unroll
        for (int kb = 0; kb < HD_; kb += 16) {
            const uint32_t qh0 = *(const uint32_t*)&sm.Qhi[(arow)    *QKH + kb + tig*2];
            const uint32_t qh1 = *(const uint32_t*)&sm.Qhi[(arow + 8)*QKH + kb + tig*2];
            const uint32_t qh2 = *(const uint32_t*)&sm.Qhi[(arow)    *QKH + kb + 8 + tig*2];
            const uint32_t qh3 = *(const uint32_t*)&sm.Qhi[(arow + 8)*QKH + kb + 8 + tig*2];
            const uint32_t ql0 = *(const uint32_t*)&sm.Qlo[(arow)    *QKH + kb + tig*2];
            const uint32_t ql1 = *(const uint32_t*)&sm.Qlo[(arow + 8)*QKH + kb + tig*2];
            const uint32_t ql2 = *(const uint32_t*)&sm.Qlo[(arow)    *QKH + kb + 8 + tig*2];
            const uint32_t ql3 = *(const uint32_t*)&sm.Qlo[(arow + 8)*QKH + kb + 8 + tig*2];
            const uint32_t k0 = *(const uint32_t*)&sm.Kh[bcol*QKH + kb + tig*2];
            const uint32_t k1 = *(const uint32_t*)&sm.Kh[bcol*QKH + kb + 8 + tig*2];
            mma_f16(sc0, sc1, sc2, sc3, qh0, qh1, qh2, qh3, k0, k1);
            mma_f16(sc0, sc1, sc2, sc3, ql0, ql1, ql2, ql3, k0, k1);
        }

        // ---- softcap + mask, exchange via Ss ----
        {
            const int c0 = warpN * 8 + tig * 2;
            const int sa = s0 + c0, sb2 = s0 + c0 + 1;
            const int qp0 = sm.pos[arow], qp1 = sm.pos[arow + 8];
            const float v0 = SOFTCAP * fast_tanh(sc0 * (1.0f / SOFTCAP));
            const float v1 = SOFTCAP * fast_tanh(sc1 * (1.0f / SOFTCAP));
            const float v2 = SOFTCAP * fast_tanh(sc2 * (1.0f / SOFTCAP));
            const float v3 = SOFTCAP * fast_tanh(sc3 * (1.0f / SOFTCAP));
            sm.Ss[(arow)    *SSS + c0    ] = (sa  <= qp0 && qp0 - sa  < WIN_) ? v0 : NEGINF;
            sm.Ss[(arow)    *SSS + c0 + 1] = (sb2 <= qp0 && qp0 - sb2 < WIN_) ? v1 : NEGINF;
            sm.Ss[(arow + 8)*SSS + c0    ] = (sa  <= qp1 && qp1 - sa  < WIN_) ? v2 : NEGINF;
            sm.Ss[(arow + 8)*SSS + c0 + 1] = (sb2 <= qp1 && qp1 - sb2 < WIN_) ? v3 : NEGINF;
        }
        __syncthreads();                               // sync A: Ss ready

        // ---- register softmax ----
        float s0v[8], s1v[8];
#pragma unroll
        for (int g = 0; g < 4; g++) {
            const float2 a = *(const float2*)&sm.Ss[(arow)    *SSS + g * 8 + tig * 2];
            const float2 c = *(const float2*)&sm.Ss[(arow + 8)*SSS + g * 8 + tig * 2];
            s0v[g*2] = a.x; s0v[g*2+1] = a.y;
            s1v[g*2] = c.x; s1v[g*2+1] = c.y;
        }
        float mx0 = s0v[0], mx1 = s1v[0];
#pragma unroll
        for (int i = 1; i < 8; i++) { mx0 = fmaxf(mx0, s0v[i]); mx1 = fmaxf(mx1, s1v[i]); }
        mx0 = fmaxf(mx0, __shfl_xor_sync(0xffffffffu, mx0, 1));
        mx0 = fmaxf(mx0, __shfl_xor_sync(0xffffffffu, mx0, 2));
        mx1 = fmaxf(mx1, __shfl_xor_sync(0xffffffffu, mx1, 1));
        mx1 = fmaxf(mx1, __shfl_xor_sync(0xffffffffu, mx1, 2));

        const float mn0 = fmaxf(m0, mx0);
        const float mn1 = fmaxf(m1, mx1);
        const float a0 = __expf(m0 - mn0);
        const float a1 = __expf(m1 - mn1);

        float p0[8], p1[8];
        float ls0 = 0.0f, ls1 = 0.0f;
#pragma unroll
        for (int i = 0; i < 8; i++) {
            p0[i] = __expf(s0v[i] - mn0);
            p1[i] = __expf(s1v[i] - mn1);
            ls0 += p0[i]; ls1 += p1[i];
        }
        ls0 += __shfl_xor_sync(0xffffffffu, ls0, 1);
        ls0 += __shfl_xor_sync(0xffffffffu, ls0, 2);
        ls1 += __shfl_xor_sync(0xffffffffu, ls1, 1);
        ls1 += __shfl_xor_sync(0xffffffffu, ls1, 2);

        m0 = mn0; m1 = mn1;
        l0r = l0r * a0 + ls0;
        l1r = l1r * a1 + ls1;

        // ---- rescale O, pack P fragments, P @ V ----
#pragma unroll
        for (int nf = 0; nf < 8; nf++) {
            o[nf][0] *= a0; o[nf][1] *= a0;
            o[nf][2] *= a1; o[nf][3] *= a1;
        }
#pragma unroll
        for (int ks = 0; ks < 2; ks++) {
            const int kb = ks * 16;
            const uint32_t pa0 = h2_as_u32(__floats2half2_rn(p0[ks*4+0], p0[ks*4+1]));
            const uint32_t pa1 = h2_as_u32(__floats2half2_rn(p1[ks*4+0], p1[ks*4+1]));
            const uint32_t pa2 = h2_as_u32(__floats2half2_rn(p0[ks*4+2], p0[ks*4+3]));
            const uint32_t pa3 = h2_as_u32(__floats2half2_rn(p1[ks*4+2], p1[ks*4+3]));
#pragma unroll
            for (int nf = 0; nf < 8; nf++) {
                const int col = warpN * 64 + nf * 8 + gid;
                const uint32_t b0 = *(const uint32_t*)&sm.Vt[col*VTS + kb + tig*2];
                const uint32_t b1 = *(const uint32_t*)&sm.Vt[col*VTS + kb + 8 + tig*2];
                mma_f16(o[nf][0], o[nf][1], o[nf][2], o[nf][3],
                        pa0, pa1, pa2, pa3, b0, b1);
            }
        }
        __syncthreads();                               // sync B: tile reads done

        if (has_next) {
            store_kv();                                // commit prefetched tile
            __syncthreads();                           // sync C: new tile visible
        }
    }

    const float li0 = 1.0f / l0r;
    const float li1 = 1.0f / l1r;
    const int row0g = q0 + arow;
#pragma unroll
    for (int nf = 0; nf < 8; nf++) {
        const int col = warpN * 64 + nf * 8 + tig * 2;
        __half* p0 = g_attn + (((size_t)b * T_ + row0g)     * NH_ + h) * HD_ + col;
        __half* p1 = g_attn + (((size_t)b * T_ + row0g + 8) * NH_ + h) * HD_ + col;
        *(half2*)p0 = __floats2half2_rn(o[nf][0] * li0, o[nf][1] * li0);
        *(half2*)p1 = __floats2half2_rn(o[nf][2] * li1, o[nf][3] * li1);
    }
}

// ---------------- launcher ----------------------------------------------------------
extern "C" void kernel_launch(void* const* d_in, const int* in_sizes, int n_in,
                              void* d_out, int out_size)
{
    const float* x      = (const float*)d_in[0];
    const int*   seg    = (const int*)  d_in[1];
    const int*   cur    = (const int*)  d_in[2];
    const float* wq     = (const float*)d_in[3];
    const float* wk     = (const float*)d_in[4];
    const float* wv     = (const float*)d_in[5];
    const float* wo     = (const float*)d_in[6];
    const float* qns    = (const float*)d_in[7];
    const float* kns    = (const float*)d_in[8];
    const float* kcache = (const float*)d_in[9];
    const float* vcache = (const float*)d_in[10];
    float* out = (float*)d_out;

    float *qkvp;
    __half *xh, *wqkvT, *woT, *attnp;
    cudaGetSymbolAddress((void**)&qkvp,  g_qkv);
    cudaGetSymbolAddress((void**)&xh,    g_xh);
    cudaGetSymbolAddress((void**)&wqkvT, g_wqkvT);
    cudaGetSymbolAddress((void**)&woT,   g_woT);
    cudaGetSymbolAddress((void**)&attnp, g_attn);

    const int M = B_ * T_;

    f2h<<<((B_*T_*D_/4) + 255)/256, 256>>>(x, xh, B_*T_*D_/4);
    wtrans_h<<<dim3(2048/32, D_/32), dim3(32,8)>>>(wq, wqkvT,                   D_, 2048);
    wtrans_h<<<dim3(1024/32, D_/32), dim3(32,8)>>>(wk, wqkvT + (size_t)2048*D_, D_, 1024);
    wtrans_h<<<dim3(1024/32, D_/32), dim3(32,8)>>>(wv, wqkvT + (size_t)3072*D_, D_, 1024);
    wtrans_h<<<dim3(D_/32, (NH_*HD_)/32), dim3(32,8)>>>(wo, woT, NH_*HD_, D_);

    rope_table_kernel<<<(SC_ * 128) / 256, 256>>>();

    cudaFuncSetAttribute(gemm_f16, cudaFuncAttributeMaxDynamicSharedMemorySize, GSMEM);

    gemm_f16<<<dim3(QKVW/128, M/128), 256, GSMEM>>>(xh, wqkvT, qkvp, M, QKVW, D_);

    merge_k<<<(B_*SC_*NKV_*HD_/4)/256, 256>>>(kcache);
    vtrans_cache<<<dim3(SC_/32, HD_/32, B_*NKV_), dim3(32,8)>>>(vcache, cur);

    // one warp per (bt, head): B*T*(NH+NKV) warps / 8 per block
    normrope_warp<<<(M * (NH_ + NKV_)) / 8, 256>>>(qkvp, qns, kns, seg, cur);

    cudaFuncSetAttribute(attn_f16, cudaFuncAttributeMaxDynamicSharedMemorySize,
                         (int)sizeof(AttnSmemH));
    attn_f16<<<dim3(T_/32, NH_, B_), 256, sizeof(AttnSmemH)>>>(seg);

    gemm_f16<<<dim3(D_/128, M/128), 256, GSMEM>>>(attnp, woT, out, M, D_, NH_*HD_);
}

// round 17
// speedup vs baseline: 1.1115x; 1.0457x over previous
#include <cuda_runtime.h>
#include <cuda_fp16.h>
#include <math.h>
#include <stdint.h>

#define B_      2
#define T_      2048
#define D_      2048
#define NH_     8
#define NKV_    4
#define HD_     256
#define SC_     2048
#define WIN_    512
#define SOFTCAP 50.0f
#define NEGINF  -2.3819763e38f
#define QKVW    4096

// ---------------- scratch (device globals; no allocation allowed) ------------
__device__ float  g_qkv[(size_t)B_*T_*QKVW];
__device__ __half g_xh[(size_t)B_*T_*D_];
__device__ __half g_wqkvT[(size_t)QKVW*D_];
__device__ __half g_woT[(size_t)D_*(NH_*HD_)];
__device__ __half g_attn[(size_t)B_*T_*NH_*HD_];
__device__ __half g_kch[(size_t)B_*SC_*NKV_*HD_];
__device__ __half g_vct[(size_t)B_*NKV_*HD_*SC_];
__device__ float2 g_rope[(size_t)SC_*128];

// ---------------- helpers -------------------------------------------------------
__device__ __forceinline__ uint32_t h2_as_u32(half2 h) {
    return *(uint32_t*)&h;
}

__device__ __forceinline__ void mma_f16(float& d0, float& d1, float& d2, float& d3,
                                        uint32_t a0, uint32_t a1, uint32_t a2, uint32_t a3,
                                        uint32_t b0, uint32_t b1) {
    asm volatile("mma.sync.aligned.m16n8k16.row.col.f32.f16.f16.f32 "
                 "{%0,%1,%2,%3}, {%4,%5,%6,%7}, {%8,%9}, {%0,%1,%2,%3};"
                 : "+f"(d0), "+f"(d1), "+f"(d2), "+f"(d3)
                 : "r"(a0), "r"(a1), "r"(a2), "r"(a3), "r"(b0), "r"(b1));
}

__device__ __forceinline__ void ldmatrix_x4(uint32_t& r0, uint32_t& r1,
                                            uint32_t& r2, uint32_t& r3, uint32_t saddr) {
    asm volatile("ldmatrix.sync.aligned.m8n8.x4.shared.b16 {%0,%1,%2,%3}, [%4];"
                 : "=r"(r0), "=r"(r1), "=r"(r2), "=r"(r3) : "r"(saddr));
}

__device__ __forceinline__ void cpasync16(uint32_t saddr, const void* gptr) {
    asm volatile("cp.async.cg.shared.global [%0], [%1], 16;\n" :: "r"(saddr), "l"(gptr));
}
__device__ __forceinline__ void cpasync_commit() { asm volatile("cp.async.commit_group;"); }
__device__ __forceinline__ void cpasync_wait0()  { asm volatile("cp.async.wait_group 0;"); }
__device__ __forceinline__ void cpasync_wait1()  { asm volatile("cp.async.wait_group 1;"); }

__device__ __forceinline__ float fast_tanh(float x) {
    float xc = fminf(fmaxf(x, -15.0f), 15.0f);
    float e = __expf(-2.0f * xc);
    return (1.0f - e) / (1.0f + e);
}

// ---------------- preprocessing ---------------------------------------------------
__global__ void f2h(const float* __restrict__ in, __half* __restrict__ out, int n4)
{
    const int i = blockIdx.x * 256 + threadIdx.x;
    if (i < n4) {
        float4 v = ((const float4*)in)[i];
        half2 h0 = __floats2half2_rn(v.x, v.y);
        half2 h1 = __floats2half2_rn(v.z, v.w);
        half2* dst = (half2*)(out + (size_t)i * 4);
        dst[0] = h0; dst[1] = h1;
    }
}

__global__ void wtrans_h(const float* __restrict__ w, __half* __restrict__ wt, int K, int N)
{
    __shared__ float tile[32][33];
    const int n0 = blockIdx.x * 32, k0 = blockIdx.y * 32;
    const int tx = threadIdx.x, ty = threadIdx.y;
#pragma unroll
    for (int i = 0; i < 32; i += 8)
        tile[ty + i][tx] = w[(size_t)(k0 + ty + i) * N + n0 + tx];
    __syncthreads();
#pragma unroll
    for (int i = 0; i < 32; i += 8)
        wt[(size_t)(n0 + ty + i) * K + k0 + tx] = __float2half_rn(tile[tx][ty + i]);
}

// ---------------- fp16 tensor-core GEMM (BK=32, 3-stage, ldmatrix) ------------------
#define AST2 40
#define STG2 (128 * AST2)
#define GSMEM (3 * 2 * STG2 * 2)

__global__ void __launch_bounds__(256) gemm_f16(const __half* __restrict__ A,
                                                const __half* __restrict__ Bt,
                                                float* __restrict__ C,
                                                int M, int N, int K)
{
    extern __shared__ __half hs[];
    __half* As = hs;
    __half* Bs = hs + 3 * STG2;

    const int tid  = threadIdx.x;
    const int warp = tid >> 5;
    const int lane = tid & 31;
    const int warpM = warp >> 2;
    const int warpN = warp & 3;
    const int gid = lane >> 2;
    const int tig = lane & 3;

    const int row0 = blockIdx.y * 128;
    const int col0 = blockIdx.x * 128;

    uint32_t sA = (uint32_t)__cvta_generic_to_shared(As);
    uint32_t sB = (uint32_t)__cvta_generic_to_shared(Bs);

    const int ld_r = tid >> 1;
    const int ld_c = (tid & 1) * 2;

    const int a_lrow   = lane & 15;
    const int a_lchunk = (lane >> 4) * 8;
    const int b_lrow   = (lane & 7) + ((lane >> 4) << 3);
    const int b_lchunk = ((lane >> 3) & 1) * 8;

    const int ntiles = K / 32;

    auto load_tile = [&](int kt, int st) {
#pragma unroll
        for (int c = 0; c < 2; c++) {
            cpasync16(sA + (uint32_t)(st * STG2 + ld_r * AST2) * 2 + (ld_c + c) * 16,
                      A + (size_t)(row0 + ld_r) * K + kt * 32 + (ld_c + c) * 8);
            cpasync16(sB + (uint32_t)(st * STG2 + ld_r * AST2) * 2 + (ld_c + c) * 16,
                      Bt + (size_t)(col0 + ld_r) * K + kt * 32 + (ld_c + c) * 8);
        }
    };

    float acc[4][4][4];
#pragma unroll
    for (int i = 0; i < 4; i++)
#pragma unroll
        for (int j = 0; j < 4; j++)
#pragma unroll
            for (int r = 0; r < 4; r++) acc[i][j][r] = 0.0f;

    load_tile(0, 0);
    cpasync_commit();
    load_tile(1, 1);
    cpasync_commit();

    for (int kt = 0; kt < ntiles; kt++) {
        const int st = kt % 3;
        if (kt + 1 < ntiles) cpasync_wait1(); else cpasync_wait0();
        __syncthreads();

        const uint32_t sAst = sA + (uint32_t)(st * STG2) * 2;
        const uint32_t sBst = sB + (uint32_t)(st * STG2) * 2;

#pragma unroll
        for (int ks = 0; ks < 2; ks++) {
            const int kb = ks * 16;
            uint32_t bf[4][2];
#pragma unroll
            for (int p = 0; p < 2; p++) {
                const uint32_t baddr = sBst +
                    (uint32_t)((warpN * 32 + p * 16 + b_lrow) * AST2 + kb + b_lchunk) * 2;
                ldmatrix_x4(bf[2*p][0], bf[2*p][1], bf[2*p+1][0], bf[2*p+1][1], baddr);
            }
#pragma unroll
            for (int mt = 0; mt < 4; mt++) {
                const int rb = warpM * 64 + mt * 16;
                uint32_t a0, a1, a2, a3;
                const uint32_t aaddr = sAst +
                    (uint32_t)((rb + a_lrow) * AST2 + kb + a_lchunk) * 2;
                ldmatrix_x4(a0, a1, a2, a3, aaddr);
#pragma unroll
                for (int nt = 0; nt < 4; nt++)
                    mma_f16(acc[mt][nt][0], acc[mt][nt][1], acc[mt][nt][2], acc[mt][nt][3],
                            a0, a1, a2, a3, bf[nt][0], bf[nt][1]);
            }
        }

        if (kt + 2 < ntiles) {
            load_tile(kt + 2, (kt + 2) % 3);
            cpasync_commit();
        }
    }

#pragma unroll
    for (int mt = 0; mt < 4; mt++) {
        const int r = row0 + warpM * 64 + mt * 16 + gid;
#pragma unroll
        for (int nt = 0; nt < 4; nt++) {
            const int c = col0 + warpN * 32 + nt * 8 + tig * 2;
            *(float2*)(C + (size_t)r * N + c)       = make_float2(acc[mt][nt][0], acc[mt][nt][1]);
            *(float2*)(C + (size_t)(r + 8) * N + c) = make_float2(acc[mt][nt][2], acc[mt][nt][3]);
        }
    }
}

// ---------------- rope table -------------------------------------------------------
__global__ void rope_table_kernel()
{
    const int idx = blockIdx.x * 256 + threadIdx.x;
    const int pos = idx >> 7;
    const int i   = idx & 127;
    const double ts  = pow(10000.0, (double)i / 128.0);
    const double ang = (double)pos / ts;
    double sn, cs;
    sincos(ang, &sn, &cs);
    g_rope[idx] = make_float2((float)cs, (float)sn);
}

// ---------------- K cache merge ------------------------------------------------------
__global__ void merge_k(const float* __restrict__ kcache)
{
    const int i = blockIdx.x * 256 + threadIdx.x;
    float4 v = ((const float4*)kcache)[i];
    half2* dst = (half2*)(g_kch + (size_t)i * 4);
    dst[0] = __floats2half2_rn(v.x, v.y);
    dst[1] = __floats2half2_rn(v.z, v.w);
}

// ---------------- V cache: select + transpose + fp16 ----------------------------------
__global__ void vtrans_cache(const float* __restrict__ vcache, const int* __restrict__ cur)
{
    __shared__ float tile[32][33];
    const int s0 = blockIdx.x * 32, d0 = blockIdx.y * 32;
    const int bk = blockIdx.z;
    const int b = bk / NKV_, kv = bk % NKV_;
    const int tx = threadIdx.x, ty = threadIdx.y;
    const int ci = *cur;
#pragma unroll
    for (int i = 0; i < 32; i += 8) {
        const int s = s0 + ty + i;
        const int t = s - ci;
        const float v = (t >= 0 && t < T_)
            ? g_qkv[((size_t)b * T_ + t) * QKVW + 3072 + kv * HD_ + d0 + tx]
            : vcache[(((size_t)b * SC_ + s) * NKV_ + kv) * HD_ + d0 + tx];
        tile[ty + i][tx] = v;
    }
    __syncthreads();
#pragma unroll
    for (int i = 0; i < 32; i += 8) {
        const int d = d0 + ty + i;
        g_vct[((size_t)(b * NKV_ + kv) * HD_ + d) * SC_ + s0 + tx] =
            __float2half_rn(tile[tx][ty + i]);
    }
}

// ---------------- RMSNorm + RoPE: one WARP per (bt, head) -----------------------------
__global__ void __launch_bounds__(256) normrope_warp(float* __restrict__ qkv,
                                                     const float* __restrict__ qns,
                                                     const float* __restrict__ kns,
                                                     const int* __restrict__ seg,
                                                     const int* __restrict__ cur)
{
    const int gw   = blockIdx.x * 8 + (threadIdx.x >> 5);
    const int lane = threadIdx.x & 31;
    const int bt = gw / (NH_ + NKV_);
    const int hy = gw - bt * (NH_ + NKV_);

    const bool is_k = hy >= NH_;
    const int h = is_k ? hy - NH_ : hy;
    const int in_off = is_k ? 2048 : 0;
    const float* scale = is_k ? kns : qns;

    float* base = qkv + (size_t)bt * QKVW + in_off + h * HD_;
    const float4 va = *(const float4*)(base + lane * 4);
    const float4 vb = *(const float4*)(base + 128 + lane * 4);

    float ss = va.x*va.x + va.y*va.y + va.z*va.z + va.w*va.w
             + vb.x*vb.x + vb.y*vb.y + vb.z*vb.z + vb.w*vb.w;
#pragma unroll
    for (int o = 16; o; o >>= 1) ss += __shfl_xor_sync(0xffffffffu, ss, o);
    const float msi = rsqrtf(ss * (1.0f / (float)HD_) + 1e-6f);

    const float4 sa = *(const float4*)(scale + lane * 4);
    const float4 sb = *(const float4*)(scale + 128 + lane * 4);

    float n1[4], n2[4];
    n1[0] = va.x * msi * (1.0f + sa.x);
    n1[1] = va.y * msi * (1.0f + sa.y);
    n1[2] = va.z * msi * (1.0f + sa.z);
    n1[3] = va.w * msi * (1.0f + sa.w);
    n2[0] = vb.x * msi * (1.0f + sb.x);
    n2[1] = vb.y * msi * (1.0f + sb.y);
    n2[2] = vb.z * msi * (1.0f + sb.z);
    n2[3] = vb.w * msi * (1.0f + sb.w);

    int pos = seg[bt];
    if (pos < 0) pos = 0;
    if (pos > SC_ - 1) pos = SC_ - 1;

    float r1[4], r2[4];
#pragma unroll
    for (int j = 0; j < 4; j++) {
        const float2 cs = g_rope[pos * 128 + lane * 4 + j];
        r1[j] = n1[j] * cs.x - n2[j] * cs.y;
        r2[j] = n2[j] * cs.x + n1[j] * cs.y;
    }

    if (is_k) {
        const int b = bt / T_, t = bt - b * T_;
        const int slot = *cur + t;
        if (slot < SC_) {
            __half* kb = g_kch + (((size_t)b * SC_ + slot) * NKV_ + h) * HD_;
            *(half2*)(kb + lane * 4)       = __floats2half2_rn(r1[0], r1[1]);
            *(half2*)(kb + lane * 4 + 2)   = __floats2half2_rn(r1[2], r1[3]);
            *(half2*)(kb + 128 + lane * 4)     = __floats2half2_rn(r2[0], r2[1]);
            *(half2*)(kb + 128 + lane * 4 + 2) = __floats2half2_rn(r2[2], r2[3]);
        }
    } else {
        *(float4*)(base + lane * 4)       = make_float4(r1[0], r1[1], r1[2], r1[3]);
        *(float4*)(base + 128 + lane * 4) = make_float4(r2[0], r2[1], r2[2], r2[3]);
    }
}

// ---------------- fp16 flash attention: plain-fp16 QK, reg softmax, prefetch -----------
#define QKH 264
#define VTS 40
#define SSS 36

struct AttnSmemH {
    __half Qh [32 * QKH];
    __half Kh [32 * QKH];
    __half Vt [256 * VTS];
    float  Ss [32 * SSS];
    int   pos[32];
    int   srange[2];
};

__global__ void __launch_bounds__(256, 2) attn_f16(const int* __restrict__ seg)
{
    extern __shared__ char smem_raw[];
    AttnSmemH& sm = *reinterpret_cast<AttnSmemH*>(smem_raw);

    const int tid  = threadIdx.x;
    const int warp = tid >> 5;
    const int lane = tid & 31;
    const int gid  = lane >> 2;
    const int tig  = lane & 3;
    const int warpM = warp >> 2;
    const int warpN = warp & 3;

    const int q0 = blockIdx.x * 32;
    const int h  = blockIdx.y;
    const int b  = blockIdx.z;
    const int kvh = h / (NH_ / NKV_);

    const float* qbase = g_qkv + ((size_t)b * T_ + q0) * QKVW + h * HD_;
    const float qscale = 0.0625f;
#pragma unroll
    for (int j = 0; j < 8; j++) {
        const int fi = tid + j * 256;
        const int r = fi >> 6, c4 = (fi & 63) * 4;
        float4 v = *(const float4*)(qbase + (size_t)r * QKVW + c4);
        *(half2*)&sm.Qh[r*QKH + c4]     = __floats2half2_rn(v.x * qscale, v.y * qscale);
        *(half2*)&sm.Qh[r*QKH + c4 + 2] = __floats2half2_rn(v.z * qscale, v.w * qscale);
    }
    if (tid < 32)
        sm.pos[tid] = seg[b * T_ + q0 + tid];
    __syncthreads();
    if (tid == 0) {
        int mn = sm.pos[0], mx = sm.pos[0];
        for (int j = 1; j < 32; j++) { mn = min(mn, sm.pos[j]); mx = max(mx, sm.pos[j]); }
        int lo = mn - (WIN_ - 1); if (lo < 0) lo = 0;
        int hi = mx; if (hi > SC_ - 1) hi = SC_ - 1;
        sm.srange[0] = lo & ~31;
        sm.srange[1] = hi;
    }
    __syncthreads();
    const int s_lo = sm.srange[0], s_hi = sm.srange[1];

    const int arow = warpM * 16 + gid;

    float m0 = -1e30f, m1 = -1e30f, l0r = 0.0f, l1r = 0.0f;

    float o[8][4];
#pragma unroll
    for (int nf = 0; nf < 8; nf++)
#pragma unroll
        for (int r = 0; r < 4; r++) o[nf][r] = 0.0f;

    const __half* khbase = g_kch + ((size_t)b * SC_ * NKV_ + kvh) * HD_;
    const __half* vtbase = g_vct + (size_t)(b * NKV_ + kvh) * HD_ * SC_;

    uint4 kpre[4], vpre[4];
    const int k_r[4]  = { (tid+0) >> 5, (tid+256) >> 5, (tid+512) >> 5, (tid+768) >> 5 };
    const int k_c8    = (tid & 31) * 8;
    const int v_d[4]  = { (tid+0) >> 2, (tid+256) >> 2, (tid+512) >> 2, (tid+768) >> 2 };
    const int v_c8    = (tid & 3) * 8;

    auto load_kv = [&](int s0) {
#pragma unroll
        for (int j = 0; j < 4; j++) {
            kpre[j] = *(const uint4*)(khbase + (size_t)(s0 + k_r[j]) * NKV_ * HD_ + k_c8);
            vpre[j] = *(const uint4*)(vtbase + (size_t)v_d[j] * SC_ + s0 + v_c8);
        }
    };
    auto store_kv = [&]() {
#pragma unroll
        for (int j = 0; j < 4; j++) {
            *(uint4*)&sm.Kh[k_r[j]*QKH + k_c8] = kpre[j];
            *(uint4*)&sm.Vt[v_d[j]*VTS + v_c8] = vpre[j];
        }
    };

    load_kv(s_lo);
    store_kv();
    __syncthreads();

    for (int s0 = s_lo; s0 <= s_hi; s0 += 32) {
        const bool has_next = (s0 + 32) <= s_hi;
        if (has_next) load_kv(s0 + 32);

        // ---- QK^T (plain fp16) ----
        float sc0 = 0.f, sc1 = 0.f, sc2 = 0.f, sc3 = 0.f;
        const int bcol = warpN * 8 + gid;
#pragma unroll
        for (int kb = 0; kb < HD_; kb += 16) {
            const uint32_t q0f = *(const uint32_t*)&sm.Qh[(arow)    *QKH + kb + tig*2];
            const uint32_t q1f = *(const uint32_t*)&sm.Qh[(arow + 8)*QKH + kb + tig*2];
            const uint32_t q2f = *(const uint32_t*)&sm.Qh[(arow)    *QKH + kb + 8 + tig*2];
            const uint32_t q3f = *(const uint32_t*)&sm.Qh[(arow + 8)*QKH + kb + 8 + tig*2];
            const uint32_t k0 = *(const uint32_t*)&sm.Kh[bcol*QKH + kb + tig*2];
            const uint32_t k1 = *(const uint32_t*)&sm.Kh[bcol*QKH + kb + 8 + tig*2];
            mma_f16(sc0, sc1, sc2, sc3, q0f, q1f, q2f, q3f, k0, k1);
        }

        // ---- softcap + mask, exchange via Ss ----
        {
            const int c0 = warpN * 8 + tig * 2;
            const int sa = s0 + c0, sb2 = s0 + c0 + 1;
            const int qp0 = sm.pos[arow], qp1 = sm.pos[arow + 8];
            const float v0 = SOFTCAP * fast_tanh(sc0 * (1.0f / SOFTCAP));
            const float v1 = SOFTCAP * fast_tanh(sc1 * (1.0f / SOFTCAP));
            const float v2 = SOFTCAP * fast_tanh(sc2 * (1.0f / SOFTCAP));
            const float v3 = SOFTCAP * fast_tanh(sc3 * (1.0f / SOFTCAP));
            sm.Ss[(arow)    *SSS + c0    ] = (sa  <= qp0 && qp0 - sa  < WIN_) ? v0 : NEGINF;
            sm.Ss[(arow)    *SSS + c0 + 1] = (sb2 <= qp0 && qp0 - sb2 < WIN_) ? v1 : NEGINF;
            sm.Ss[(arow + 8)*SSS + c0    ] = (sa  <= qp1 && qp1 - sa  < WIN_) ? v2 : NEGINF;
            sm.Ss[(arow + 8)*SSS + c0 + 1] = (sb2 <= qp1 && qp1 - sb2 < WIN_) ? v3 : NEGINF;
        }
        __syncthreads();                               // sync A

        // ---- register softmax ----
        float s0v[8], s1v[8];
#pragma unroll
        for (int g = 0; g < 4; g++) {
            const float2 a = *(const float2*)&sm.Ss[(arow)    *SSS + g * 8 + tig * 2];
            const float2 c = *(const float2*)&sm.Ss[(arow + 8)*SSS + g * 8 + tig * 2];
            s0v[g*2] = a.x; s0v[g*2+1] = a.y;
            s1v[g*2] = c.x; s1v[g*2+1] = c.y;
        }
        float mx0 = s0v[0], mx1 = s1v[0];
#pragma unroll
        for (int i = 1; i < 8; i++) { mx0 = fmaxf(mx0, s0v[i]); mx1 = fmaxf(mx1, s1v[i]); }
        mx0 = fmaxf(mx0, __shfl_xor_sync(0xffffffffu, mx0, 1));
        mx0 = fmaxf(mx0, __shfl_xor_sync(0xffffffffu, mx0, 2));
        mx1 = fmaxf(mx1, __shfl_xor_sync(0xffffffffu, mx1, 1));
        mx1 = fmaxf(mx1, __shfl_xor_sync(0xffffffffu, mx1, 2));

        const float mn0 = fmaxf(m0, mx0);
        const float mn1 = fmaxf(m1, mx1);
        const float a0 = __expf(m0 - mn0);
        const float a1 = __expf(m1 - mn1);

        float p0[8], p1[8];
        float ls0 = 0.0f, ls1 = 0.0f;
#pragma unroll
        for (int i = 0; i < 8; i++) {
            p0[i] = __expf(s0v[i] - mn0);
            p1[i] = __expf(s1v[i] - mn1);
            ls0 += p0[i]; ls1 += p1[i];
        }
        ls0 += __shfl_xor_sync(0xffffffffu, ls0, 1);
        ls0 += __shfl_xor_sync(0xffffffffu, ls0, 2);
        ls1 += __shfl_xor_sync(0xffffffffu, ls1, 1);
        ls1 += __shfl_xor_sync(0xffffffffu, ls1, 2);

        m0 = mn0; m1 = mn1;
        l0r = l0r * a0 + ls0;
        l1r = l1r * a1 + ls1;

        // ---- rescale O, pack P fragments, P @ V ----
#pragma unroll
        for (int nf = 0; nf < 8; nf++) {
            o[nf][0] *= a0; o[nf][1] *= a0;
            o[nf][2] *= a1; o[nf][3] *= a1;
        }
#pragma unroll
        for (int ks = 0; ks < 2; ks++) {
            const int kb = ks * 16;
            const uint32_t pa0 = h2_as_u32(__floats2half2_rn(p0[ks*4+0], p0[ks*4+1]));
            const uint32_t pa1 = h2_as_u32(__floats2half2_rn(p1[ks*4+0], p1[ks*4+1]));
            const uint32_t pa2 = h2_as_u32(__floats2half2_rn(p0[ks*4+2], p0[ks*4+3]));
            const uint32_t pa3 = h2_as_u32(__floats2half2_rn(p1[ks*4+2], p1[ks*4+3]));
#pragma unroll
            for (int nf = 0; nf < 8; nf++) {
                const int col = warpN * 64 + nf * 8 + gid;
                const uint32_t b0 = *(const uint32_t*)&sm.Vt[col*VTS + kb + tig*2];
                const uint32_t b1 = *(const uint32_t*)&sm.Vt[col*VTS + kb + 8 + tig*2];
                mma_f16(o[nf][0], o[nf][1], o[nf][2], o[nf][3],
                        pa0, pa1, pa2, pa3, b0, b1);
            }
        }
        __syncthreads();                               // sync B

        if (has_next) {
            store_kv();
            __syncthreads();                           // sync C
        }
    }

    const float li0 = 1.0f / l0r;
    const float li1 = 1.0f / l1r;
    const int row0g = q0 + arow;
#pragma unroll
    for (int nf = 0; nf < 8; nf++) {
        const int col = warpN * 64 + nf * 8 + tig * 2;
        __half* p0 = g_attn + (((size_t)b * T_ + row0g)     * NH_ + h) * HD_ + col;
        __half* p1 = g_attn + (((size_t)b * T_ + row0g + 8) * NH_ + h) * HD_ + col;
        *(half2*)p0 = __floats2half2_rn(o[nf][0] * li0, o[nf][1] * li0);
        *(half2*)p1 = __floats2half2_rn(o[nf][2] * li1, o[nf][3] * li1);
    }
}

// ---------------- launcher ----------------------------------------------------------
extern "C" void kernel_launch(void* const* d_in, const int* in_sizes, int n_in,
                              void* d_out, int out_size)
{
    const float* x      = (const float*)d_in[0];
    const int*   seg    = (const int*)  d_in[1];
    const int*   cur    = (const int*)  d_in[2];
    const float* wq     = (const float*)d_in[3];
    const float* wk     = (const float*)d_in[4];
    const float* wv     = (const float*)d_in[5];
    const float* wo     = (const float*)d_in[6];
    const float* qns    = (const float*)d_in[7];
    const float* kns    = (const float*)d_in[8];
    const float* kcache = (const float*)d_in[9];
    const float* vcache = (const float*)d_in[10];
    float* out = (float*)d_out;

    float *qkvp;
    __half *xh, *wqkvT, *woT, *attnp;
    cudaGetSymbolAddress((void**)&qkvp,  g_qkv);
    cudaGetSymbolAddress((void**)&xh,    g_xh);
    cudaGetSymbolAddress((void**)&wqkvT, g_wqkvT);
    cudaGetSymbolAddress((void**)&woT,   g_woT);
    cudaGetSymbolAddress((void**)&attnp, g_attn);

    const int M = B_ * T_;

    f2h<<<((B_*T_*D_/4) + 255)/256, 256>>>(x, xh, B_*T_*D_/4);
    wtrans_h<<<dim3(2048/32, D_/32), dim3(32,8)>>>(wq, wqkvT,                   D_, 2048);
    wtrans_h<<<dim3(1024/32, D_/32), dim3(32,8)>>>(wk, wqkvT + (size_t)2048*D_, D_, 1024);
    wtrans_h<<<dim3(1024/32, D_/32), dim3(32,8)>>>(wv, wqkvT + (size_t)3072*D_, D_, 1024);
    wtrans_h<<<dim3(D_/32, (NH_*HD_)/32), dim3(32,8)>>>(wo, woT, NH_*HD_, D_);

    rope_table_kernel<<<(SC_ * 128) / 256, 256>>>();

    cudaFuncSetAttribute(gemm_f16, cudaFuncAttributeMaxDynamicSharedMemorySize, GSMEM);

    gemm_f16<<<dim3(QKVW/128, M/128), 256, GSMEM>>>(xh, wqkvT, qkvp, M, QKVW, D_);

    merge_k<<<(B_*SC_*NKV_*HD_/4)/256, 256>>>(kcache);
    vtrans_cache<<<dim3(SC_/32, HD_/32, B_*NKV_), dim3(32,8)>>>(vcache, cur);

    normrope_warp<<<(M * (NH_ + NKV_)) / 8, 256>>>(qkvp, qns, kns, seg, cur);

    cudaFuncSetAttribute(attn_f16, cudaFuncAttributeMaxDynamicSharedMemorySize,
                         (int)sizeof(AttnSmemH));
    attn_f16<<<dim3(T_/32, NH_, B_), 256, sizeof(AttnSmemH)>>>(seg);

    gemm_f16<<<dim3(D_/128, M/128), 256, GSMEM>>>(attnp, woT, out, M, D_, NH_*HD_);
}